// round 1
// baseline (speedup 1.0000x reference)
#include <cuda_runtime.h>
#include <cuda_bf16.h>

#define FEAT   24
#define NPIX   (FEAT*FEAT)        // 576
#define KANCH  9
#define NN     (NPIX*KANCH)       // 5184
#define MIDCH  24
#define CINCH  512
#define NWORD  81                 // 5184 / 64
#define SORTSZ 8192
#define IMGW   384.0f
#define IMGH   384.0f
#define NMS_T  0.7f
#define MINSZ  16.0f
#define KCHUNKS 16                // 512 / 32
#define CPART  32

// ---------------- scratch (device globals; no allocation allowed) -------------
__device__ float g_hpart[KCHUNKS * MIDCH * NPIX];
__device__ float g_h[MIDCH * NPIX];

__device__ float g_x0[NN], g_y0[NN], g_x1[NN], g_y1[NN];
__device__ float g_ws[NN], g_hs[NN], g_prob[NN];
__device__ unsigned g_valid[NN];
__device__ unsigned long long g_keys[SORTSZ];

__device__ float g_bx0[NN], g_by0[NN], g_bx1[NN], g_by1[NN], g_barea[NN];
__device__ unsigned g_bvalid[NN];
__device__ int g_order[NN];

__device__ unsigned long long g_mask[NN * NWORD];
__device__ unsigned g_keepsorted[NN];
__device__ unsigned g_keep[NN];

// ---------------- 1. conv 3x3, 512->24, partial over K chunks -----------------
__global__ void conv_part_kernel(const float* __restrict__ x,
                                 const float* __restrict__ W) {
    const int y  = blockIdx.x;          // 0..23
    const int kc = blockIdx.y;          // 0..15
    const int c0 = kc * CPART;

    __shared__ float xs[CPART][3][26];          // width 26: embedded horiz zero-pad
    __shared__ float ws[MIDCH][CPART][9];

    const int tid = threadIdx.x;        // 576 threads

    for (int idx = tid; idx < CPART * 3 * 26; idx += 576) {
        int c  = idx / 78;
        int r  = (idx % 78) / 26;
        int xx = idx % 26;
        int gy = y + r - 1;
        int gx = xx - 1;
        float v = 0.0f;
        if (gy >= 0 && gy < FEAT && gx >= 0 && gx < FEAT)
            v = x[(c0 + c) * NPIX + gy * FEAT + gx];
        xs[c][r][xx] = v;
    }
    for (int idx = tid; idx < MIDCH * CPART * 9; idx += 576) {
        int o = idx / (CPART * 9);
        int c = (idx % (CPART * 9)) / 9;
        int t = idx % 9;
        ws[o][c][t] = W[((o * CINCH) + c0 + c) * 9 + t];
    }
    __syncthreads();

    const int xc = tid % FEAT;
    const int o  = tid / FEAT;
    float acc = 0.0f;
    #pragma unroll 4
    for (int c = 0; c < CPART; c++) {
        float a0 = xs[c][0][xc], a1 = xs[c][0][xc+1], a2 = xs[c][0][xc+2];
        float b0 = xs[c][1][xc], b1 = xs[c][1][xc+1], b2 = xs[c][1][xc+2];
        float d0 = xs[c][2][xc], d1 = xs[c][2][xc+1], d2 = xs[c][2][xc+2];
        const float* w = ws[o][c];
        acc += a0*w[0] + a1*w[1] + a2*w[2]
             + b0*w[3] + b1*w[4] + b2*w[5]
             + d0*w[6] + d1*w[7] + d2*w[8];
    }
    g_hpart[kc * (MIDCH*NPIX) + o * NPIX + y * FEAT + xc] = acc;
}

__global__ void conv_reduce_kernel(const float* __restrict__ b) {
    int i = blockIdx.x * blockDim.x + threadIdx.x;   // < 13824
    if (i >= MIDCH * NPIX) return;
    float s = 0.0f;
    #pragma unroll
    for (int k = 0; k < KCHUNKS; k++) s += g_hpart[k * (MIDCH*NPIX) + i];
    s += b[i / NPIX];
    g_h[i] = fmaxf(s, 0.0f);
}

// ---------------- 2. heads + anchor decode + sort-key pack --------------------
__global__ void decode_kernel(const float* __restrict__ Wc, const float* __restrict__ bc,
                              const float* __restrict__ Wr, const float* __restrict__ br,
                              const float* __restrict__ anchors,
                              float* __restrict__ out) {
    int p = blockIdx.x * blockDim.x + threadIdx.x;
    if (p >= NPIX) return;

    float hv[MIDCH];
    #pragma unroll
    for (int o = 0; o < MIDCH; o++) hv[o] = g_h[o * NPIX + p];

    float cls[2*KANCH];
    float reg[4*KANCH];
    #pragma unroll
    for (int q = 0; q < 2*KANCH; q++) {
        float s = 0.0f;
        #pragma unroll
        for (int o = 0; o < MIDCH; o++) s += hv[o] * Wc[q * MIDCH + o];
        cls[q] = s + bc[q];
    }
    #pragma unroll
    for (int q = 0; q < 4*KANCH; q++) {
        float s = 0.0f;
        #pragma unroll
        for (int o = 0; o < MIDCH; o++) s += hv[o] * Wr[q * MIDCH + o];
        reg[q] = s + br[q];
    }

    #pragma unroll
    for (int k = 0; k < KANCH; k++) {
        int n = p * KANCH + k;
        float c0 = cls[2*k], c1 = cls[2*k+1];
        out[4*NN + 2*n]     = c0;
        out[4*NN + 2*n + 1] = c1;
        float prob = 1.0f / (1.0f + expf(c0 - c1));   // softmax[:,1]

        float ax = anchors[4*n], ay = anchors[4*n+1];
        float aw = anchors[4*n+2], ah = anchors[4*n+3];
        float tx = reg[4*k], ty = reg[4*k+1], tw = reg[4*k+2], th = reg[4*k+3];

        float px = ax + aw * tx;
        float py = ay + ah * ty;
        float pw = aw * expf(tw);
        float ph = ah * expf(th);
        out[4*n]   = px; out[4*n+1] = py;
        out[4*n+2] = pw; out[4*n+3] = ph;

        float x0 = px - 0.5f * (pw - 1.0f);
        float y0 = py - 0.5f * (ph - 1.0f);
        float x1 = pw + x0 - 1.0f;
        float y1 = ph + y0 - 1.0f;
        x0 = fminf(fmaxf(x0, 0.0f), IMGW - 1.0f);
        x1 = fminf(fmaxf(x1, 0.0f), IMGW - 1.0f);
        y0 = fminf(fmaxf(y0, 0.0f), IMGH - 1.0f);
        y1 = fminf(fmaxf(y1, 0.0f), IMGH - 1.0f);
        float wsv = x1 - x0 + 1.0f;
        float hsv = y1 - y0 + 1.0f;

        // recompute valid_mask from anchors (bit-exact vs numpy fp32)
        float ax0 = ax - 0.5f * (aw - 1.0f);
        float ay0 = ay - 0.5f * (ah - 1.0f);
        float ax1 = aw + ax0 - 1.0f;
        float ay1 = ah + ay0 - 1.0f;
        bool anchor_valid = (ax0 >= 0.0f) && (ay0 >= 0.0f) && (ax1 < IMGW) && (ay1 < IMGH);
        bool valid = anchor_valid && (wsv >= MINSZ) && (hsv >= MINSZ);

        float score = valid ? prob : -1.0f;
        float f = -score;                                // ascending f == descending score
        unsigned u = __float_as_uint(f);
        u = (u & 0x80000000u) ? ~u : (u | 0x80000000u);  // monotone encode
        g_keys[n] = ((unsigned long long)u << 32) | (unsigned)n;

        g_x0[n] = x0; g_y0[n] = y0; g_x1[n] = x1; g_y1[n] = y1;
        g_ws[n] = wsv; g_hs[n] = hsv; g_prob[n] = prob;
        g_valid[n] = valid ? 1u : 0u;
    }
}

// ---------------- 3. bitonic sort of 8192 u64 keys (one block) ----------------
__global__ __launch_bounds__(1024) void sort_kernel() {
    extern __shared__ unsigned long long s[];
    const int tid = threadIdx.x;
    for (int i = tid; i < SORTSZ; i += 1024)
        s[i] = (i < NN) ? g_keys[i] : 0xFFFFFFFFFFFFFFFFull;
    __syncthreads();
    for (int k = 2; k <= SORTSZ; k <<= 1) {
        for (int j = k >> 1; j > 0; j >>= 1) {
            for (int i = tid; i < SORTSZ; i += 1024) {
                int ixj = i ^ j;
                if (ixj > i) {
                    bool up = ((i & k) == 0);
                    unsigned long long a = s[i], bb = s[ixj];
                    if ((a > bb) == up) { s[i] = bb; s[ixj] = a; }
                }
            }
            __syncthreads();
        }
    }
    for (int i = tid; i < NN; i += 1024) g_keys[i] = s[i];
}

// ---------------- 4. gather boxes into sorted order ---------------------------
__global__ void gather_kernel() {
    int i = blockIdx.x * blockDim.x + threadIdx.x;
    if (i >= NN) return;
    int j = (int)(unsigned)(g_keys[i] & 0xFFFFFFFFull);
    g_order[i] = j;
    g_bx0[i] = g_x0[j];
    g_by0[i] = g_y0[j];
    g_bx1[i] = g_x1[j];
    g_by1[i] = g_y1[j];
    g_barea[i] = g_ws[j] * g_hs[j];
    g_bvalid[i] = g_valid[j];
}

// ---------------- 5. suppression bitmask matrix --------------------------------
__global__ void mask_kernel() {
    const int rb = blockIdx.y, cb = blockIdx.x;
    const int t  = threadIdx.x;          // 64 threads
    const int i  = rb * 64 + t;

    __shared__ float cx0[64], cy0[64], cx1[64], cy1[64], car[64];
    if (cb >= rb) {
        int j = cb * 64 + t;
        cx0[t] = g_bx0[j]; cy0[t] = g_by0[j];
        cx1[t] = g_bx1[j]; cy1[t] = g_by1[j];
        car[t] = g_barea[j];
    }
    __syncthreads();

    unsigned long long w = 0ull;
    if (cb >= rb && g_bvalid[i]) {
        float x0 = g_bx0[i], y0 = g_by0[i], x1 = g_bx1[i], y1 = g_by1[i];
        float ar = g_barea[i];
        int jbase = cb * 64;
        #pragma unroll 8
        for (int b = 0; b < 64; b++) {
            int j = jbase + b;
            if (j > i) {
                float iw = fminf(x1, cx1[b]) - fmaxf(x0, cx0[b]) + 1.0f;
                float ih = fminf(y1, cy1[b]) - fmaxf(y0, cy0[b]) + 1.0f;
                iw = fmaxf(iw, 0.0f);
                ih = fmaxf(ih, 0.0f);
                float inter = iw * ih;
                float iou = inter / (ar + car[b] - inter);
                if (iou > NMS_T) w |= (1ull << b);
            }
        }
    }
    g_mask[(size_t)i * NWORD + cb] = w;
}

// ---------------- 6. exact greedy NMS reduce (one block) ----------------------
__global__ __launch_bounds__(128) void nms_reduce_kernel() {
    __shared__ unsigned long long remv[NWORD];
    __shared__ unsigned long long diag[64];
    __shared__ unsigned long long sh_keep;
    __shared__ unsigned vball[2];

    const int tid = threadIdx.x;        // 128
    for (int w = tid; w < NWORD; w += 128) remv[w] = 0ull;
    __syncthreads();

    for (int c = 0; c < NWORD; c++) {
        if (tid < 64) {
            int i = c * 64 + tid;
            diag[tid] = g_mask[(size_t)i * NWORD + c];
            unsigned vb = __ballot_sync(0xFFFFFFFFu, g_bvalid[i] != 0u);
            if ((tid & 31) == 0) vball[tid >> 5] = vb;
        }
        __syncthreads();

        if (tid == 0) {
            unsigned long long vm =
                ((unsigned long long)vball[1] << 32) | (unsigned long long)vball[0];
            unsigned long long avail = vm & ~remv[c];
            unsigned long long keepw = 0ull;
            while (avail) {
                int b = __ffsll((long long)avail) - 1;
                keepw |= (1ull << b);
                avail &= ~(diag[b] | (1ull << b));
            }
            sh_keep = keepw;
        }
        __syncthreads();

        unsigned long long keepw = sh_keep;
        if (tid < 64)
            g_keepsorted[c * 64 + tid] = (unsigned)((keepw >> tid) & 1ull);

        if (keepw) {
            for (int w = c + 1 + tid; w < NWORD; w += 128) {
                unsigned long long acc = 0ull;
                unsigned long long kk = keepw;
                while (kk) {
                    int b = __ffsll((long long)kk) - 1;
                    kk &= kk - 1;
                    acc |= g_mask[(size_t)(c * 64 + b) * NWORD + w];
                }
                remv[w] |= acc;
            }
        }
        __syncthreads();
    }
}

// ---------------- 7. scatter keep back to original order ----------------------
__global__ void scatter_kernel() {
    int i = blockIdx.x * blockDim.x + threadIdx.x;
    if (i >= NN) return;
    g_keep[g_order[i]] = g_keepsorted[i];
}

// ---------------- 8. finalize outputs ------------------------------------------
__global__ void finalize_kernel(const int* __restrict__ labels,
                                float* __restrict__ out) {
    int n = blockIdx.x * blockDim.x + threadIdx.x;
    if (n >= NN) return;
    unsigned kp = g_keep[n];
    float kf = kp ? 1.0f : 0.0f;
    float x0 = g_x0[n], y0 = g_y0[n];
    float wsv = g_ws[n], hsv = g_hs[n];
    out[6*NN + 4*n]     = (x0 + 0.5f * (wsv - 1.0f)) * kf;
    out[6*NN + 4*n + 1] = (y0 + 0.5f * (hsv - 1.0f)) * kf;
    out[6*NN + 4*n + 2] = wsv * kf;
    out[6*NN + 4*n + 3] = hsv * kf;
    out[10*NN + n] = g_prob[n] * kf;
    out[11*NN + n] = kp ? (float)labels[n] : 0.0f;
    out[12*NN + n] = kf;
}

// -------------------------------------------------------------------------------
extern "C" void kernel_launch(void* const* d_in, const int* in_sizes, int n_in,
                              void* d_out, int out_size) {
    const float* x       = (const float*)d_in[0];
    const int*   labels  = (const int*)  d_in[1];
    const float* Wrpn    = (const float*)d_in[2];
    const float* brpn    = (const float*)d_in[3];
    const float* Wc      = (const float*)d_in[4];
    const float* bc      = (const float*)d_in[5];
    const float* Wr      = (const float*)d_in[6];
    const float* br      = (const float*)d_in[7];
    const float* anchors = (const float*)d_in[8];
    float* out = (float*)d_out;

    // 64KB dynamic smem for the sort (above the 48KB default)
    cudaFuncSetAttribute(sort_kernel,
                         cudaFuncAttributeMaxDynamicSharedMemorySize,
                         SORTSZ * (int)sizeof(unsigned long long));

    conv_part_kernel<<<dim3(FEAT, KCHUNKS), 576>>>(x, Wrpn);
    conv_reduce_kernel<<<(MIDCH * NPIX + 255) / 256, 256>>>(brpn);
    decode_kernel<<<(NPIX + 63) / 64, 64>>>(Wc, bc, Wr, br, anchors, out);
    sort_kernel<<<1, 1024, SORTSZ * sizeof(unsigned long long)>>>();
    gather_kernel<<<(NN + 127) / 128, 128>>>();
    mask_kernel<<<dim3(NWORD, NWORD), 64>>>();
    nms_reduce_kernel<<<1, 128>>>();
    scatter_kernel<<<(NN + 127) / 128, 128>>>();
    finalize_kernel<<<(NN + 127) / 128, 128>>>(labels, out);
}

// round 2
// speedup vs baseline: 1.6586x; 1.6586x over previous
#include <cuda_runtime.h>
#include <cuda_bf16.h>

#define FEAT   24
#define NPIX   (FEAT*FEAT)        // 576
#define KANCH  9
#define NN     (NPIX*KANCH)       // 5184
#define MIDCH  24
#define CINCH  512
#define NWORD  81                 // 5184 / 64
#define IMGW   384.0f
#define IMGH   384.0f
#define NMS_T  0.7f
#define MINSZ  16.0f
#define KCHUNKS 16                // 512 / 32
#define CPART  32
#define ST     1024               // sort threads
#define NTILES 6                  // ceil(5184/1024); last tile = 64 elems (2 full warps)

typedef unsigned long long u64;

// ---------------- scratch (device globals; no allocation allowed) -------------
__device__ float g_hpart[KCHUNKS * MIDCH * NPIX];
__device__ float g_h[MIDCH * NPIX];

__device__ float g_x0[NN], g_y0[NN], g_x1[NN], g_y1[NN];
__device__ float g_ws[NN], g_hs[NN], g_prob[NN];
__device__ unsigned g_valid[NN];
__device__ u64 g_keys[NN];

__device__ float g_bx0[NN], g_by0[NN], g_bx1[NN], g_by1[NN], g_barea[NN];
__device__ unsigned g_bvalid[NN];
__device__ int g_order[NN];

__device__ u64 g_mask[NN * NWORD];
__device__ unsigned g_keepsorted[NN];

// ---------------- 1. conv 3x3, 512->24, partial over K chunks -----------------
__global__ void conv_part_kernel(const float* __restrict__ x,
                                 const float* __restrict__ W) {
    const int y  = blockIdx.x;          // 0..23
    const int kc = blockIdx.y;          // 0..15
    const int c0 = kc * CPART;

    __shared__ float xs[CPART][3][26];
    __shared__ float ws[MIDCH][CPART][9];

    const int tid = threadIdx.x;        // 576 threads

    for (int idx = tid; idx < CPART * 3 * 26; idx += 576) {
        int c  = idx / 78;
        int r  = (idx % 78) / 26;
        int xx = idx % 26;
        int gy = y + r - 1;
        int gx = xx - 1;
        float v = 0.0f;
        if (gy >= 0 && gy < FEAT && gx >= 0 && gx < FEAT)
            v = x[(c0 + c) * NPIX + gy * FEAT + gx];
        xs[c][r][xx] = v;
    }
    for (int idx = tid; idx < MIDCH * CPART * 9; idx += 576) {
        int o = idx / (CPART * 9);
        int c = (idx % (CPART * 9)) / 9;
        int t = idx % 9;
        ws[o][c][t] = W[((o * CINCH) + c0 + c) * 9 + t];
    }
    __syncthreads();

    const int xc = tid % FEAT;
    const int o  = tid / FEAT;
    float acc = 0.0f;
    #pragma unroll 4
    for (int c = 0; c < CPART; c++) {
        float a0 = xs[c][0][xc], a1 = xs[c][0][xc+1], a2 = xs[c][0][xc+2];
        float b0 = xs[c][1][xc], b1 = xs[c][1][xc+1], b2 = xs[c][1][xc+2];
        float d0 = xs[c][2][xc], d1 = xs[c][2][xc+1], d2 = xs[c][2][xc+2];
        const float* w = ws[o][c];
        acc += a0*w[0] + a1*w[1] + a2*w[2]
             + b0*w[3] + b1*w[4] + b2*w[5]
             + d0*w[6] + d1*w[7] + d2*w[8];
    }
    g_hpart[kc * (MIDCH*NPIX) + o * NPIX + y * FEAT + xc] = acc;
}

__global__ void conv_reduce_kernel(const float* __restrict__ b) {
    int i = blockIdx.x * blockDim.x + threadIdx.x;
    if (i >= MIDCH * NPIX) return;
    float s = 0.0f;
    #pragma unroll
    for (int k = 0; k < KCHUNKS; k++) s += g_hpart[k * (MIDCH*NPIX) + i];
    s += b[i / NPIX];
    g_h[i] = fmaxf(s, 0.0f);
}

// ---------------- 2. heads + anchor decode + sort-key pack --------------------
// One thread per anchor: 18 blocks x 288 threads (32 pixels x 9 anchors)
__global__ __launch_bounds__(288) void decode_kernel(
        const float* __restrict__ Wc, const float* __restrict__ bc,
        const float* __restrict__ Wr, const float* __restrict__ br,
        const float* __restrict__ anchors,
        float* __restrict__ out) {
    __shared__ float sh[32][MIDCH];
    __shared__ float sWc[2*KANCH*MIDCH];
    __shared__ float sWr[4*KANCH*MIDCH];
    __shared__ float sbc[2*KANCH];
    __shared__ float sbr[4*KANCH];

    const int tid = threadIdx.x;
    const int p0  = blockIdx.x * 32;

    for (int i = tid; i < 32 * MIDCH; i += 288) {
        int ch = i / 32, pp = i % 32;
        sh[pp][ch] = g_h[ch * NPIX + p0 + pp];
    }
    for (int i = tid; i < 2*KANCH*MIDCH; i += 288) sWc[i] = Wc[i];
    for (int i = tid; i < 4*KANCH*MIDCH; i += 288) sWr[i] = Wr[i];
    if (tid < 2*KANCH) sbc[tid] = bc[tid];
    if (tid < 4*KANCH) sbr[tid] = br[tid];
    __syncthreads();

    const int lp = tid / KANCH;          // 0..31
    const int k  = tid % KANCH;
    const int p  = p0 + lp;
    const int n  = p * KANCH + k;

    float hv[MIDCH];
    #pragma unroll
    for (int o = 0; o < MIDCH; o++) hv[o] = sh[lp][o];

    float c0 = 0.0f, c1 = 0.0f;
    #pragma unroll
    for (int o = 0; o < MIDCH; o++) {
        c0 += hv[o] * sWc[(2*k)   * MIDCH + o];
        c1 += hv[o] * sWc[(2*k+1) * MIDCH + o];
    }
    c0 += sbc[2*k]; c1 += sbc[2*k+1];

    float tx = 0.0f, ty = 0.0f, tw = 0.0f, th = 0.0f;
    #pragma unroll
    for (int o = 0; o < MIDCH; o++) {
        float h = hv[o];
        tx += h * sWr[(4*k)   * MIDCH + o];
        ty += h * sWr[(4*k+1) * MIDCH + o];
        tw += h * sWr[(4*k+2) * MIDCH + o];
        th += h * sWr[(4*k+3) * MIDCH + o];
    }
    tx += sbr[4*k]; ty += sbr[4*k+1]; tw += sbr[4*k+2]; th += sbr[4*k+3];

    out[4*NN + 2*n]     = c0;
    out[4*NN + 2*n + 1] = c1;
    float prob = 1.0f / (1.0f + expf(c0 - c1));

    float ax = anchors[4*n],   ay = anchors[4*n+1];
    float aw = anchors[4*n+2], ah = anchors[4*n+3];

    float px = ax + aw * tx;
    float py = ay + ah * ty;
    float pw = aw * expf(tw);
    float ph = ah * expf(th);
    out[4*n]   = px; out[4*n+1] = py;
    out[4*n+2] = pw; out[4*n+3] = ph;

    float x0 = px - 0.5f * (pw - 1.0f);
    float y0 = py - 0.5f * (ph - 1.0f);
    float x1 = pw + x0 - 1.0f;
    float y1 = ph + y0 - 1.0f;
    x0 = fminf(fmaxf(x0, 0.0f), IMGW - 1.0f);
    x1 = fminf(fmaxf(x1, 0.0f), IMGW - 1.0f);
    y0 = fminf(fmaxf(y0, 0.0f), IMGH - 1.0f);
    y1 = fminf(fmaxf(y1, 0.0f), IMGH - 1.0f);
    float wsv = x1 - x0 + 1.0f;
    float hsv = y1 - y0 + 1.0f;

    float ax0 = ax - 0.5f * (aw - 1.0f);
    float ay0 = ay - 0.5f * (ah - 1.0f);
    float ax1 = aw + ax0 - 1.0f;
    float ay1 = ah + ay0 - 1.0f;
    bool anchor_valid = (ax0 >= 0.0f) && (ay0 >= 0.0f) && (ax1 < IMGW) && (ay1 < IMGH);
    bool valid = anchor_valid && (wsv >= MINSZ) && (hsv >= MINSZ);

    float score = valid ? prob : -1.0f;
    float f = -score;
    unsigned u = __float_as_uint(f);
    u = (u & 0x80000000u) ? ~u : (u | 0x80000000u);
    g_keys[n] = ((u64)u << 32) | (unsigned)n;

    g_x0[n] = x0; g_y0[n] = y0; g_x1[n] = x1; g_y1[n] = y1;
    g_ws[n] = wsv; g_hs[n] = hsv; g_prob[n] = prob;
    g_valid[n] = valid ? 1u : 0u;
}

// ---------------- 3. single-block LSD radix sort (4x8-bit) + gather -----------
__global__ __launch_bounds__(ST) void sort_gather_kernel() {
    extern __shared__ char smraw[];
    u64* buf0 = (u64*)smraw;                       // NN
    u64* buf1 = buf0 + NN;                         // NN
    unsigned* whist   = (unsigned*)(buf1 + NN);    // 32*256
    unsigned* runbase = whist + 32*256;            // 256
    unsigned* tilecnt = runbase + 256;             // 256
    unsigned* hist    = tilecnt + 256;             // 256

    const int tid  = threadIdx.x;
    const int lane = tid & 31;
    const int warp = tid >> 5;

    for (int i = tid; i < NN; i += ST) buf0[i] = g_keys[i];

    u64* src = buf0;
    u64* dst = buf1;

    for (int pass = 0; pass < 4; pass++) {
        const int shift = 32 + pass * 8;

        if (tid < 256) hist[tid] = 0;
        for (int i = tid; i < 32*256; i += ST) whist[i] = 0;
        __syncthreads();

        for (int i = tid; i < NN; i += ST)
            atomicAdd(&hist[(unsigned)(src[i] >> shift) & 255u], 1u);
        __syncthreads();

        // exclusive scan of hist -> runbase
        unsigned v = (tid < 256) ? hist[tid] : 0u;
        if (tid < 256) runbase[tid] = v;
        __syncthreads();
        for (int off = 1; off < 256; off <<= 1) {
            unsigned t = (tid < 256 && tid >= off) ? runbase[tid - off] : 0u;
            __syncthreads();
            if (tid < 256) runbase[tid] += t;
            __syncthreads();
        }
        if (tid < 256) runbase[tid] -= v;
        __syncthreads();

        for (int tile = 0; tile < NTILES; tile++) {
            const int idx = tile * ST + tid;
            const bool warp_active = (tile * ST + warp * 32) < NN;  // warps fully act/inact
            u64 key = 0; unsigned digit = 0; int rank = 0;

            if (warp_active) {
                key = src[idx];
                digit = (unsigned)(key >> shift) & 255u;
                unsigned eq = 0xFFFFFFFFu;
                #pragma unroll
                for (int b = 0; b < 8; b++) {
                    unsigned bal = __ballot_sync(0xFFFFFFFFu, (digit >> b) & 1u);
                    eq &= ((digit >> b) & 1u) ? bal : ~bal;
                }
                rank = __popc(eq & ((1u << lane) - 1u));
                if (rank == 0) whist[warp * 256 + digit] = __popc(eq);
            }
            __syncthreads();

            if (tid < 256) {
                unsigned s = 0;
                #pragma unroll
                for (int w = 0; w < 32; w++) {
                    unsigned t2 = whist[w * 256 + tid];
                    whist[w * 256 + tid] = s;
                    s += t2;
                }
                tilecnt[tid] = s;
            }
            __syncthreads();

            if (warp_active) {
                unsigned pos = runbase[digit] + whist[warp * 256 + digit] + (unsigned)rank;
                dst[pos] = key;
            }
            __syncthreads();

            if (tid < 256) runbase[tid] += tilecnt[tid];
            for (int i = tid; i < 32*256; i += ST) whist[i] = 0;
            __syncthreads();
        }

        u64* tmp = src; src = dst; dst = tmp;
    }

    // gather boxes into sorted order
    for (int i = tid; i < NN; i += ST) {
        u64 kk = src[i];
        int j = (int)(unsigned)(kk & 0xFFFFFFFFull);
        g_order[i]  = j;
        g_bx0[i]    = g_x0[j];
        g_by0[i]    = g_y0[j];
        g_bx1[i]    = g_x1[j];
        g_by1[i]    = g_y1[j];
        g_barea[i]  = g_ws[j] * g_hs[j];
        g_bvalid[i] = g_valid[j];
    }
}

// ---------------- 4. suppression bitmask matrix --------------------------------
__global__ void mask_kernel() {
    const int rb = blockIdx.y, cb = blockIdx.x;
    const int t  = threadIdx.x;          // 64 threads
    const int i  = rb * 64 + t;
    if (cb < rb) { g_mask[(size_t)i * NWORD + cb] = 0ull; return; }

    __shared__ float cx0[64], cy0[64], cx1[64], cy1[64], car[64];
    {
        int j = cb * 64 + t;
        cx0[t] = g_bx0[j]; cy0[t] = g_by0[j];
        cx1[t] = g_bx1[j]; cy1[t] = g_by1[j];
        car[t] = g_barea[j];
    }
    __syncthreads();

    u64 w = 0ull;
    if (g_bvalid[i]) {
        float x0 = g_bx0[i], y0 = g_by0[i], x1 = g_bx1[i], y1 = g_by1[i];
        float ar = g_barea[i];
        int jbase = cb * 64;
        #pragma unroll 8
        for (int b = 0; b < 64; b++) {
            int j = jbase + b;
            if (j > i) {
                float iw = fminf(x1, cx1[b]) - fmaxf(x0, cx0[b]) + 1.0f;
                float ih = fminf(y1, cy1[b]) - fmaxf(y0, cy0[b]) + 1.0f;
                iw = fmaxf(iw, 0.0f);
                ih = fmaxf(ih, 0.0f);
                float inter = iw * ih;
                float iou = inter / (ar + car[b] - inter);
                if (iou > NMS_T) w |= (1ull << b);
            }
        }
    }
    g_mask[(size_t)i * NWORD + cb] = w;
}

// ---------------- 5. exact greedy NMS reduce (one block) ----------------------
#define RT 256
__global__ __launch_bounds__(RT) void nms_reduce_kernel() {
    __shared__ u64 remv[NWORD];
    __shared__ u64 sdiag[64];
    __shared__ u64 vword[NWORD];
    __shared__ u64 sh_keep;
    __shared__ int kb[64];
    __shared__ int kcnt;
    __shared__ unsigned vhalf[NWORD * 2];

    const int tid  = threadIdx.x;
    const int lane = tid & 31;

    for (int w = tid; w < NWORD; w += RT) remv[w] = 0ull;
    for (int i = tid; i < NN; i += RT) {
        unsigned bal = __ballot_sync(0xFFFFFFFFu, g_bvalid[i] != 0u);
        if (lane == 0) vhalf[i >> 5] = bal;
    }
    __syncthreads();
    for (int w = tid; w < NWORD; w += RT)
        vword[w] = ((u64)vhalf[2*w+1] << 32) | (u64)vhalf[2*w];

    u64 rd = 0ull;
    if (tid < 64) rd = g_mask[(size_t)tid * NWORD + 0];
    __syncthreads();

    for (int c = 0; c < NWORD; c++) {
        if (tid < 64) sdiag[tid] = rd;
        __syncthreads();
        // prefetch next chunk's diag while this chunk is processed
        if (tid < 64 && c + 1 < NWORD)
            rd = g_mask[(size_t)((c+1)*64 + tid) * NWORD + (c+1)];

        if (tid == 0) {
            u64 avail = vword[c] & ~remv[c];
            u64 keepw = 0ull;
            int n = 0;
            while (avail) {
                int b = __ffsll((long long)avail) - 1;
                keepw |= (1ull << b);
                kb[n++] = b;
                avail &= ~(sdiag[b] | (1ull << b));
            }
            sh_keep = keepw;
            kcnt = n;
        }
        __syncthreads();

        u64 keepw = sh_keep;
        int n = kcnt;
        if (tid < 64)
            g_keepsorted[c * 64 + tid] = (unsigned)((keepw >> tid) & 1ull);

        if (n) {
            const size_t rowc = (size_t)c * 64;
            for (int w = c + 1 + tid; w < NWORD; w += RT) {
                u64 acc = 0ull;
                int q = 0;
                for (; q + 4 <= n; q += 4) {
                    u64 a0 = g_mask[(rowc + kb[q])   * NWORD + w];
                    u64 a1 = g_mask[(rowc + kb[q+1]) * NWORD + w];
                    u64 a2 = g_mask[(rowc + kb[q+2]) * NWORD + w];
                    u64 a3 = g_mask[(rowc + kb[q+3]) * NWORD + w];
                    acc |= a0 | a1 | a2 | a3;
                }
                for (; q < n; q++) acc |= g_mask[(rowc + kb[q]) * NWORD + w];
                remv[w] |= acc;
            }
        }
        __syncthreads();
    }
}

// ---------------- 6. finalize (fused scatter) ----------------------------------
__global__ void finalize_kernel(const int* __restrict__ labels,
                                float* __restrict__ out) {
    int i = blockIdx.x * blockDim.x + threadIdx.x;
    if (i >= NN) return;
    int n = g_order[i];
    unsigned kp = g_keepsorted[i];
    float kf = kp ? 1.0f : 0.0f;
    float x0 = g_x0[n], y0 = g_y0[n];
    float wsv = g_ws[n], hsv = g_hs[n];
    out[6*NN + 4*n]     = (x0 + 0.5f * (wsv - 1.0f)) * kf;
    out[6*NN + 4*n + 1] = (y0 + 0.5f * (hsv - 1.0f)) * kf;
    out[6*NN + 4*n + 2] = wsv * kf;
    out[6*NN + 4*n + 3] = hsv * kf;
    out[10*NN + n] = g_prob[n] * kf;
    out[11*NN + n] = kp ? (float)labels[n] : 0.0f;
    out[12*NN + n] = kf;
}

// -------------------------------------------------------------------------------
extern "C" void kernel_launch(void* const* d_in, const int* in_sizes, int n_in,
                              void* d_out, int out_size) {
    const float* x       = (const float*)d_in[0];
    const int*   labels  = (const int*)  d_in[1];
    const float* Wrpn    = (const float*)d_in[2];
    const float* brpn    = (const float*)d_in[3];
    const float* Wc      = (const float*)d_in[4];
    const float* bc      = (const float*)d_in[5];
    const float* Wr      = (const float*)d_in[6];
    const float* br      = (const float*)d_in[7];
    const float* anchors = (const float*)d_in[8];
    float* out = (float*)d_out;

    const int sort_smem = NN * 2 * (int)sizeof(u64)        // ping-pong keys
                        + 32 * 256 * (int)sizeof(unsigned) // whist
                        + 3 * 256 * (int)sizeof(unsigned); // runbase/tilecnt/hist
    cudaFuncSetAttribute(sort_gather_kernel,
                         cudaFuncAttributeMaxDynamicSharedMemorySize, sort_smem);

    conv_part_kernel<<<dim3(FEAT, KCHUNKS), 576>>>(x, Wrpn);
    conv_reduce_kernel<<<(MIDCH * NPIX + 255) / 256, 256>>>(brpn);
    decode_kernel<<<NPIX / 32, 288>>>(Wc, bc, Wr, br, anchors, out);
    sort_gather_kernel<<<1, ST, sort_smem>>>();
    mask_kernel<<<dim3(NWORD, NWORD), 64>>>();
    nms_reduce_kernel<<<1, 128 /*unused*/ + 128>>>();   // RT=256 threads
    finalize_kernel<<<(NN + 127) / 128, 128>>>(labels, out);
}

// round 3
// speedup vs baseline: 2.1920x; 1.3216x over previous
#include <cuda_runtime.h>
#include <cuda_bf16.h>

#define FEAT   24
#define NPIX   (FEAT*FEAT)        // 576
#define KANCH  9
#define NN     (NPIX*KANCH)       // 5184
#define MIDCH  24
#define CINCH  512
#define NWORD  81                 // 5184 / 64
#define IMGW   384.0f
#define IMGH   384.0f
#define NMS_T  0.7f
#define MINSZ  16.0f
#define KCHUNKS 16                // 512 / 32
#define CPART  32
#define NSLICE 8
#define SLICE  (NN / NSLICE)      // 648

typedef unsigned long long u64;

// ---------------- scratch (device globals; no allocation allowed) -------------
__device__ float g_hpart[KCHUNKS * MIDCH * NPIX];

__device__ float g_x0[NN], g_y0[NN], g_x1[NN], g_y1[NN];
__device__ float g_ws[NN], g_hs[NN], g_prob[NN];
__device__ unsigned g_valid[NN];
__device__ u64 g_keys[NN];
__device__ int g_rankpart[NSLICE * NN];

__device__ float g_bx0[NN], g_by0[NN], g_bx1[NN], g_by1[NN], g_barea[NN];
__device__ unsigned g_bvalid[NN];
__device__ int g_order[NN];

__device__ u64 g_mask[NN * NWORD];
__device__ unsigned g_keepsorted[NN];

// ---------------- 1. conv 3x3, 512->24, partial over K chunks -----------------
__global__ void conv_part_kernel(const float* __restrict__ x,
                                 const float* __restrict__ W) {
    const int y  = blockIdx.x;          // 0..23
    const int kc = blockIdx.y;          // 0..15
    const int c0 = kc * CPART;

    __shared__ float xs[CPART][3][26];
    __shared__ float ws[MIDCH][CPART][9];

    const int tid = threadIdx.x;        // 576 threads

    for (int idx = tid; idx < CPART * 3 * 26; idx += 576) {
        int c  = idx / 78;
        int r  = (idx % 78) / 26;
        int xx = idx % 26;
        int gy = y + r - 1;
        int gx = xx - 1;
        float v = 0.0f;
        if (gy >= 0 && gy < FEAT && gx >= 0 && gx < FEAT)
            v = x[(c0 + c) * NPIX + gy * FEAT + gx];
        xs[c][r][xx] = v;
    }
    for (int idx = tid; idx < MIDCH * CPART * 9; idx += 576) {
        int o = idx / (CPART * 9);
        int c = (idx % (CPART * 9)) / 9;
        int t = idx % 9;
        ws[o][c][t] = W[((o * CINCH) + c0 + c) * 9 + t];
    }
    __syncthreads();

    const int xc = tid % FEAT;
    const int o  = tid / FEAT;
    float acc = 0.0f;
    #pragma unroll 4
    for (int c = 0; c < CPART; c++) {
        float a0 = xs[c][0][xc], a1 = xs[c][0][xc+1], a2 = xs[c][0][xc+2];
        float b0 = xs[c][1][xc], b1 = xs[c][1][xc+1], b2 = xs[c][1][xc+2];
        float d0 = xs[c][2][xc], d1 = xs[c][2][xc+1], d2 = xs[c][2][xc+2];
        const float* w = ws[o][c];
        acc += a0*w[0] + a1*w[1] + a2*w[2]
             + b0*w[3] + b1*w[4] + b2*w[5]
             + d0*w[6] + d1*w[7] + d2*w[8];
    }
    g_hpart[kc * (MIDCH*NPIX) + o * NPIX + y * FEAT + xc] = acc;
}

// ---------------- 2. heads + decode (conv-reduce fused) -----------------------
__global__ __launch_bounds__(288) void decode_kernel(
        const float* __restrict__ Wc, const float* __restrict__ bc,
        const float* __restrict__ Wr, const float* __restrict__ br,
        const float* __restrict__ brpn,
        const float* __restrict__ anchors,
        float* __restrict__ out) {
    __shared__ float sh[32][MIDCH];
    __shared__ float sWc[2*KANCH*MIDCH];
    __shared__ float sWr[4*KANCH*MIDCH];
    __shared__ float sbc[2*KANCH];
    __shared__ float sbr[4*KANCH];

    const int tid = threadIdx.x;
    const int p0  = blockIdx.x * 32;

    // fused conv reduce + bias + relu
    for (int i = tid; i < 32 * MIDCH; i += 288) {
        int ch = i / 32, pp = i % 32;
        float s = 0.0f;
        #pragma unroll
        for (int kc = 0; kc < KCHUNKS; kc++)
            s += g_hpart[kc * (MIDCH*NPIX) + ch * NPIX + p0 + pp];
        sh[pp][ch] = fmaxf(s + brpn[ch], 0.0f);
    }
    for (int i = tid; i < 2*KANCH*MIDCH; i += 288) sWc[i] = Wc[i];
    for (int i = tid; i < 4*KANCH*MIDCH; i += 288) sWr[i] = Wr[i];
    if (tid < 2*KANCH) sbc[tid] = bc[tid];
    if (tid < 4*KANCH) sbr[tid] = br[tid];
    __syncthreads();

    const int lp = tid / KANCH;          // 0..31
    const int k  = tid % KANCH;
    const int n  = (p0 + lp) * KANCH + k;

    float hv[MIDCH];
    #pragma unroll
    for (int o = 0; o < MIDCH; o++) hv[o] = sh[lp][o];

    float c0 = 0.0f, c1 = 0.0f;
    #pragma unroll
    for (int o = 0; o < MIDCH; o++) {
        c0 += hv[o] * sWc[(2*k)   * MIDCH + o];
        c1 += hv[o] * sWc[(2*k+1) * MIDCH + o];
    }
    c0 += sbc[2*k]; c1 += sbc[2*k+1];

    float tx = 0.0f, ty = 0.0f, tw = 0.0f, th = 0.0f;
    #pragma unroll
    for (int o = 0; o < MIDCH; o++) {
        float h = hv[o];
        tx += h * sWr[(4*k)   * MIDCH + o];
        ty += h * sWr[(4*k+1) * MIDCH + o];
        tw += h * sWr[(4*k+2) * MIDCH + o];
        th += h * sWr[(4*k+3) * MIDCH + o];
    }
    tx += sbr[4*k]; ty += sbr[4*k+1]; tw += sbr[4*k+2]; th += sbr[4*k+3];

    out[4*NN + 2*n]     = c0;
    out[4*NN + 2*n + 1] = c1;
    float prob = 1.0f / (1.0f + expf(c0 - c1));

    float ax = anchors[4*n],   ay = anchors[4*n+1];
    float aw = anchors[4*n+2], ah = anchors[4*n+3];

    float px = ax + aw * tx;
    float py = ay + ah * ty;
    float pw = aw * expf(tw);
    float ph = ah * expf(th);
    out[4*n]   = px; out[4*n+1] = py;
    out[4*n+2] = pw; out[4*n+3] = ph;

    float x0 = px - 0.5f * (pw - 1.0f);
    float y0 = py - 0.5f * (ph - 1.0f);
    float x1 = pw + x0 - 1.0f;
    float y1 = ph + y0 - 1.0f;
    x0 = fminf(fmaxf(x0, 0.0f), IMGW - 1.0f);
    x1 = fminf(fmaxf(x1, 0.0f), IMGW - 1.0f);
    y0 = fminf(fmaxf(y0, 0.0f), IMGH - 1.0f);
    y1 = fminf(fmaxf(y1, 0.0f), IMGH - 1.0f);
    float wsv = x1 - x0 + 1.0f;
    float hsv = y1 - y0 + 1.0f;

    float ax0 = ax - 0.5f * (aw - 1.0f);
    float ay0 = ay - 0.5f * (ah - 1.0f);
    float ax1 = aw + ax0 - 1.0f;
    float ay1 = ah + ay0 - 1.0f;
    bool anchor_valid = (ax0 >= 0.0f) && (ay0 >= 0.0f) && (ax1 < IMGW) && (ay1 < IMGH);
    bool valid = anchor_valid && (wsv >= MINSZ) && (hsv >= MINSZ);

    float score = valid ? prob : -1.0f;
    float f = -score;
    unsigned u = __float_as_uint(f);
    u = (u & 0x80000000u) ? ~u : (u | 0x80000000u);
    g_keys[n] = ((u64)u << 32) | (unsigned)n;

    g_x0[n] = x0; g_y0[n] = y0; g_x1[n] = x1; g_y1[n] = y1;
    g_ws[n] = wsv; g_hs[n] = hsv; g_prob[n] = prob;
    g_valid[n] = valid ? 1u : 0u;
}

// ---------------- 3a. rank-by-counting partials --------------------------------
// grid (18, NSLICE), 288 threads: thread i counts keys < key[i] within slice
__global__ __launch_bounds__(288) void rank_part_kernel() {
    __shared__ u64 sk[SLICE];
    const int tid = threadIdx.x;
    const int s   = blockIdx.y;
    const int i   = blockIdx.x * 288 + tid;

    for (int j = tid; j < SLICE; j += 288) sk[j] = g_keys[s * SLICE + j];
    __syncthreads();

    const u64 key = g_keys[i];
    int cnt = 0;
    #pragma unroll 8
    for (int j = 0; j < SLICE; j++) cnt += (sk[j] < key) ? 1 : 0;
    g_rankpart[s * NN + i] = cnt;
}

// ---------------- 3b. rank reduce + scatter boxes to sorted positions ----------
__global__ void scatter_rank_kernel() {
    int i = blockIdx.x * blockDim.x + threadIdx.x;
    if (i >= NN) return;
    int r = 0;
    #pragma unroll
    for (int s = 0; s < NSLICE; s++) r += g_rankpart[s * NN + i];
    g_order[r]  = i;
    g_bx0[r]    = g_x0[i];
    g_by0[r]    = g_y0[i];
    g_bx1[r]    = g_x1[i];
    g_by1[r]    = g_y1[i];
    g_barea[r]  = g_ws[i] * g_hs[i];
    g_bvalid[r] = g_valid[i];
}

// ---------------- 4. suppression bitmask matrix (upper triangle only) ----------
__global__ void mask_kernel() {
    const int rb = blockIdx.y, cb = blockIdx.x;
    if (cb < rb) return;                 // lower triangle never read
    const int t  = threadIdx.x;          // 64 threads
    const int i  = rb * 64 + t;

    __shared__ float cx0[64], cy0[64], cx1[64], cy1[64], car[64];
    {
        int j = cb * 64 + t;
        cx0[t] = g_bx0[j]; cy0[t] = g_by0[j];
        cx1[t] = g_bx1[j]; cy1[t] = g_by1[j];
        car[t] = g_barea[j];
    }
    __syncthreads();

    u64 w = 0ull;
    if (g_bvalid[i]) {
        float x0 = g_bx0[i], y0 = g_by0[i], x1 = g_bx1[i], y1 = g_by1[i];
        float ar = g_barea[i];
        int jbase = cb * 64;
        #pragma unroll 8
        for (int b = 0; b < 64; b++) {
            int j = jbase + b;
            if (j > i) {
                float iw = fminf(x1, cx1[b]) - fmaxf(x0, cx0[b]) + 1.0f;
                float ih = fminf(y1, cy1[b]) - fmaxf(y0, cy0[b]) + 1.0f;
                iw = fmaxf(iw, 0.0f);
                ih = fmaxf(ih, 0.0f);
                float inter = iw * ih;
                float iou = inter / (ar + car[b] - inter);
                if (iou > NMS_T) w |= (1ull << b);
            }
        }
    }
    g_mask[(size_t)i * NWORD + cb] = w;
}

// ---------------- 5. exact greedy NMS reduce (one block, diag in smem) ---------
#define RT 256
__global__ __launch_bounds__(RT) void nms_reduce_kernel() {
    __shared__ u64 sdiag[NWORD * 64];    // 41.5 KB: all diagonal blocks
    __shared__ u64 remv[NWORD];
    __shared__ u64 vword[NWORD];
    __shared__ u64 sh_keep;
    __shared__ int kb[64];
    __shared__ int kcnt;
    __shared__ unsigned vhalf[NWORD * 2];

    const int tid  = threadIdx.x;
    const int lane = tid & 31;

    // preload all diagonal 64x64 blocks
    for (int i = tid; i < NWORD * 64; i += RT) {
        int c = i >> 6;
        sdiag[i] = g_mask[(size_t)i * NWORD + c];
    }
    for (int w = tid; w < NWORD; w += RT) remv[w] = 0ull;
    for (int i = tid; i < NN; i += RT) {
        unsigned bal = __ballot_sync(0xFFFFFFFFu, g_bvalid[i] != 0u);
        if (lane == 0) vhalf[i >> 5] = bal;
    }
    __syncthreads();
    for (int w = tid; w < NWORD; w += RT)
        vword[w] = ((u64)vhalf[2*w+1] << 32) | (u64)vhalf[2*w];
    __syncthreads();

    for (int c = 0; c < NWORD; c++) {
        if (tid == 0) {
            const u64* dg = &sdiag[c * 64];
            u64 avail = vword[c] & ~remv[c];
            u64 keepw = 0ull;
            int n = 0;
            while (avail) {
                int b = __ffsll((long long)avail) - 1;
                keepw |= (1ull << b);
                kb[n++] = b;
                avail &= ~(dg[b] | (1ull << b));
            }
            sh_keep = keepw;
            kcnt = n;
        }
        __syncthreads();

        u64 keepw = sh_keep;
        int n = kcnt;
        if (tid < 64)
            g_keepsorted[c * 64 + tid] = (unsigned)((keepw >> tid) & 1ull);

        if (n) {
            const size_t rowc = (size_t)c * 64;
            for (int w = c + 1 + tid; w < NWORD; w += RT) {
                u64 acc = 0ull;
                int q = 0;
                for (; q + 4 <= n; q += 4) {
                    u64 a0 = g_mask[(rowc + kb[q])   * NWORD + w];
                    u64 a1 = g_mask[(rowc + kb[q+1]) * NWORD + w];
                    u64 a2 = g_mask[(rowc + kb[q+2]) * NWORD + w];
                    u64 a3 = g_mask[(rowc + kb[q+3]) * NWORD + w];
                    acc |= a0 | a1 | a2 | a3;
                }
                for (; q < n; q++) acc |= g_mask[(rowc + kb[q]) * NWORD + w];
                remv[w] |= acc;
            }
        }
        __syncthreads();
    }
}

// ---------------- 6. finalize (fused scatter) ----------------------------------
__global__ void finalize_kernel(const int* __restrict__ labels,
                                float* __restrict__ out) {
    int i = blockIdx.x * blockDim.x + threadIdx.x;
    if (i >= NN) return;
    int n = g_order[i];
    unsigned kp = g_keepsorted[i];
    float kf = kp ? 1.0f : 0.0f;
    float x0 = g_x0[n], y0 = g_y0[n];
    float wsv = g_ws[n], hsv = g_hs[n];
    out[6*NN + 4*n]     = (x0 + 0.5f * (wsv - 1.0f)) * kf;
    out[6*NN + 4*n + 1] = (y0 + 0.5f * (hsv - 1.0f)) * kf;
    out[6*NN + 4*n + 2] = wsv * kf;
    out[6*NN + 4*n + 3] = hsv * kf;
    out[10*NN + n] = g_prob[n] * kf;
    out[11*NN + n] = kp ? (float)labels[n] : 0.0f;
    out[12*NN + n] = kf;
}

// -------------------------------------------------------------------------------
extern "C" void kernel_launch(void* const* d_in, const int* in_sizes, int n_in,
                              void* d_out, int out_size) {
    const float* x       = (const float*)d_in[0];
    const int*   labels  = (const int*)  d_in[1];
    const float* Wrpn    = (const float*)d_in[2];
    const float* brpn    = (const float*)d_in[3];
    const float* Wc      = (const float*)d_in[4];
    const float* bc      = (const float*)d_in[5];
    const float* Wr      = (const float*)d_in[6];
    const float* br      = (const float*)d_in[7];
    const float* anchors = (const float*)d_in[8];
    float* out = (float*)d_out;

    conv_part_kernel<<<dim3(FEAT, KCHUNKS), 576>>>(x, Wrpn);
    decode_kernel<<<NPIX / 32, 288>>>(Wc, bc, Wr, br, brpn, anchors, out);
    rank_part_kernel<<<dim3(18, NSLICE), 288>>>();
    scatter_rank_kernel<<<(NN + 255) / 256, 256>>>();
    mask_kernel<<<dim3(NWORD, NWORD), 64>>>();
    nms_reduce_kernel<<<1, RT>>>();
    finalize_kernel<<<(NN + 127) / 128, 128>>>(labels, out);
}